// round 8
// baseline (speedup 1.0000x reference)
#include <cuda_runtime.h>
#include <cstdint>

// Problem constants
#define SEQ    512
#define BATCH  64
#define INDIM  128
#define HDIM   512

// Tiling: 16 j-tiles x 8 b-groups = 128 CTAs, 1 per SM (forced via smem oversubscription)
#define JT     32            // h-columns per CTA
#define BT     8             // batch rows per CTA (== NWARP)
#define NJ     (HDIM / JT)   // 16 producers per batch group
#define NB     (BATCH / BT)  // 8 batch groups
#define NCTA   (NJ * NB)     // 128
#define THREADS 256
#define NWARP   8

#define WH_CPW ((HDIM / 4) / NWARP)   // 16 float4-chunks of K per warp (held in regs)
#define WI_C   (INDIM / 4)            // 32 float4-chunks for the Wi phase

// smem (floats): per-warp x row (phase1), per-warp h slice (phase2), reduce scratch
#define SX_PW    32                   // float4 per warp region (x row)
#define SH_STR4  17                   // float4 stride per h row (16 + 1 pad)
#define SH_PW    (BT * SH_STR4)       // 136 float4 per warp region
#define OFF_SX   0
#define N_SX     (NWARP * SX_PW * 4)          // 1024 floats
#define OFF_SH   (OFF_SX + N_SX)
#define N_SH     (NWARP * SH_PW * 4)          // 4352 floats
#define OFF_RED  (OFF_SH + N_SH)
#define RED_STRIDE 73
#define N_RED    (32 * RED_STRIDE)            // 2336 floats
// Inflate dynamic smem to 128KB so only ONE CTA fits per SM (keeps 128 CTAs on 128 SMs,
// avoids two CTAs stacking on one SM and becoming the per-step straggler).
#define SMEM_ALLOC (128 * 1024)

// Bounded spin: ~2^22 probes (~0.5s) >> any legitimate wait; converts a pathological
// stall into a wrong answer instead of a container-killing hang.
#define SPIN_LIMIT (1u << 22)

// xi scratch: xi[t][b][j] = bi[j]+bh[j] + x[t,b,:]. Wi[j,:]   (64 MB static)
__device__ float g_xi[(size_t)SEQ * BATCH * HDIM];
// Per-batch-group cumulative step flags, 128B apart; reset via cudaMemsetAsync.
__device__ unsigned g_flags[NB * 32];

// Packed dual-FMA: acc.{lo,hi} += a.{lo,hi} * b.{lo,hi}
#define FMA2(acc, a, b) \
    asm("fma.rn.f32x2 %0, %1, %2, %0;" : "+l"(acc) : "l"(a), "l"(b))

__global__ __launch_bounds__(THREADS, 1)
void rnn_regW_kernel(const float* __restrict__ x,
                     const float* __restrict__ Wi,
                     const float* __restrict__ bi,
                     const float* __restrict__ Wh,
                     const float* __restrict__ bh,
                     float* __restrict__ out)
{
    extern __shared__ float smem[];
    float* sx   = smem + OFF_SX;
    float* sh   = smem + OFF_SH;
    float* sred = smem + OFF_RED;

    const int tid  = threadIdx.x;
    const int bx   = blockIdx.x;
    const int bt   = bx / NJ;           // batch group
    const int jt   = bx % NJ;           // j tile
    const int j0   = jt * JT;
    const int b0   = bt * BT;
    const int lane = tid & 31;          // j within tile
    const int w    = tid >> 5;          // warp id: K-slice owner (ph2) / batch (ph1, reduce)
    const int lb   = lane >> 2;         // h-staging role: batch row
    const int lq   = lane & 3;          // h-staging role: quad
    const int jg   = j0 + lane;

    unsigned* flag = &g_flags[bt * 32];
    const float cb = bi[jg] + bh[jg];

    // =======================  PHASE 1: xi precompute  =======================
    // Warp w computes xi[t][b0+w][j0+lane] for all t. Wi row in registers.
    {
        ulonglong2 rwi[WI_C];                       // 128 regs, dead after phase 1
        const ulonglong2* wrow = (const ulonglong2*)(Wi + (size_t)jg * INDIM);
        #pragma unroll
        for (int c = 0; c < WI_C; c++) rwi[c] = __ldg(&wrow[c]);

        float4* sxw = (float4*)sx + w * SX_PW;      // per-warp region
        const float4* xsrc = (const float4*)x;
        float* xi_dst = g_xi + (size_t)(b0 + w) * HDIM + jg;   // + t*BATCH*HDIM

        for (int t = 0; t < SEQ; t++) {
            // Stage x[t][b0+w][:] : 32 lanes x 16B = 128 floats (coalesced LDG.128)
            sxw[lane] = xsrc[((size_t)t * BATCH + b0 + w) * (INDIM / 4) + lane];
            __syncwarp();
            unsigned long long acc = 0ull;
            const ulonglong2* sb = (const ulonglong2*)sxw;
            #pragma unroll 8
            for (int c = 0; c < WI_C; c++) {
                ulonglong2 hv = sb[c];              // broadcast
                FMA2(acc, rwi[c].x, hv.x);
                FMA2(acc, rwi[c].y, hv.y);
            }
            union { unsigned long long u; float2 f; } cv; cv.u = acc;
            xi_dst[(size_t)t * BATCH * HDIM] = cb + cv.f.x + cv.f.y;
            __syncwarp();                           // region reusable next t
        }
    }
    __syncthreads();

    // ==================  Load Wh K-slice into registers  ====================
    // Warp w owns kc in [w*16, w*16+16): per lane 16 float4 = 64 regs, persistent.
    ulonglong2 wq[WH_CPW];
    {
        const ulonglong2* whrow = (const ulonglong2*)(Wh + (size_t)jg * HDIM);
        #pragma unroll
        for (int c = 0; c < WH_CPW; c++) wq[c] = __ldg(&whrow[w * WH_CPW + c]);
    }

    float4* sh_w = (float4*)sh + w * SH_PW;         // per-warp h slice region
    const ulonglong2* sh_w2 = (const ulonglong2*)sh_w;

    // =====================  PHASE 2: recurrent loop  ========================
    for (int t = 0; t < SEQ; t++) {
        // Prefetch xi for this thread's output (j=lane, b=w); consumed after bar1
        const float xi_v =
            __ldg(&g_xi[((size_t)t * BATCH + b0 + w) * HDIM + jg]);

        unsigned long long acc2[BT];
        #pragma unroll
        for (int b = 0; b < BT; b++) acc2[b] = 0ull;

        if (t > 0) {
            // Per-warp acquire-poll (NO sleep; bounded). Producers: 16 j-tiles of group.
            if (lane == 0) {
                const unsigned target = (unsigned)(NJ * t);
                unsigned v, it = 0;
                do {
                    asm volatile("ld.acquire.gpu.global.u32 %0, [%1];"
                                 : "=r"(v) : "l"(flag) : "memory");
                } while (v < target && ++it < SPIN_LIMIT);
            }
            __syncwarp();

            // Stage own h K-slice: 8 rows x 64 floats. Lane (lb,lq): 4 LDG.128.
            const float4* hsrc = (const float4*)(out + (size_t)(t - 1) * BATCH * HDIM);
            const int colbase = w * WH_CPW;
            float4 hv0 = hsrc[(b0 + lb) * (HDIM / 4) + colbase + lq + 0];
            float4 hv1 = hsrc[(b0 + lb) * (HDIM / 4) + colbase + lq + 4];
            float4 hv2 = hsrc[(b0 + lb) * (HDIM / 4) + colbase + lq + 8];
            float4 hv3 = hsrc[(b0 + lb) * (HDIM / 4) + colbase + lq + 12];
            sh_w[lb * SH_STR4 + lq + 0]  = hv0;
            sh_w[lb * SH_STR4 + lq + 4]  = hv1;
            sh_w[lb * SH_STR4 + lq + 8]  = hv2;
            sh_w[lb * SH_STR4 + lq + 12] = hv3;
            __syncwarp();

            // h . Wh^T partials: weights from registers, h via smem broadcast
            #pragma unroll 4
            for (int c = 0; c < WH_CPW; c++) {
                const ulonglong2 wv = wq[c];
                #pragma unroll
                for (int b = 0; b < BT; b++) {
                    ulonglong2 hv = sh_w2[b * SH_STR4 + c];   // 16B broadcast
                    FMA2(acc2[b], wv.x, hv.x);
                    FMA2(acc2[b], wv.y, hv.y);
                }
            }
        }

        // Spill partials: sred[j=lane][b*8+w] (stride 73 -> conflict-free)
        #pragma unroll
        for (int b = 0; b < BT; b++) {
            union { unsigned long long u; float2 f; } c; c.u = acc2[b];
            sred[lane * RED_STRIDE + b * NWARP + w] = c.f.x + c.f.y;
        }
        __syncthreads();                             // bar 1: spill -> read

        // Reduce 8 warp-partials (thread: j=lane, b=w), add xi, tanh, store
        {
            const float* r = &sred[lane * RED_STRIDE + w * NWARP];
            float s = ((r[0] + r[1]) + (r[2] + r[3])) + ((r[4] + r[5]) + (r[6] + r[7]));
            const float val = tanhf(xi_v + s);
            out[(size_t)t * BATCH * HDIM + (b0 + w) * HDIM + jg] = val;
            if (t == SEQ - 1)   // h_last appended after h_seq
                out[(size_t)SEQ * BATCH * HDIM + (b0 + w) * HDIM + jg] = val;
        }
        __syncthreads();                             // bar 2: stores done, sred reusable
        if (tid == 0) {   // bar gives CTA-wide happens-before; release publishes all stores
            asm volatile("red.release.gpu.global.add.u32 [%0], %1;"
                         :: "l"(flag), "r"(1u) : "memory");
        }
    }
}

extern "C" void kernel_launch(void* const* d_in, const int* in_sizes, int n_in,
                              void* d_out, int out_size)
{
    const float* x  = (const float*)d_in[0];
    const float* Wi = (const float*)d_in[1];
    const float* bi = (const float*)d_in[2];
    const float* Wh = (const float*)d_in[3];
    const float* bh = (const float*)d_in[4];
    float* out = (float*)d_out;

    (void)in_sizes; (void)n_in; (void)out_size;

    void* flagsPtr = nullptr;
    cudaGetSymbolAddress(&flagsPtr, g_flags);
    cudaMemsetAsync(flagsPtr, 0, sizeof(g_flags), 0);

    cudaFuncSetAttribute(rnn_regW_kernel,
                         cudaFuncAttributeMaxDynamicSharedMemorySize, SMEM_ALLOC);
    rnn_regW_kernel<<<NCTA, THREADS, SMEM_ALLOC>>>(x, Wi, bi, Wh, bh, out);
}

// round 9
// speedup vs baseline: 1.8024x; 1.8024x over previous
#include <cuda_runtime.h>
#include <cstdint>

// Problem constants
#define SEQ    512
#define BATCH  64
#define INDIM  128
#define HDIM   512

// Two interleaved chains per CTA: chain = batch group of 4.
// CTA (q, jt): q in 0..7 selects group pair (2q, 2q+1), jt in 0..15 selects 32 j-cols.
#define NJ      16                 // j tiles (producers per group)
#define NQ      8                  // group pairs
#define NGRP    16                 // batch groups (4 batches each)
#define BPG     4                  // batches per group
#define NCTA    (NQ * NJ)          // 128 (<=148 SMs -> wave-1, one per SM)
#define THREADS 256
#define NWARP   8

// Per-warp K slices: Wh 64 floats (16 float4), Wi 16 floats (4 float4) - in REGISTERS
#define WHC 16
#define WIC 4

// smem (all static, ~15.5 KB)
#define SH_ROW  17                 // float4 stride per h row (16 + 1 pad)
#define SH_PW   (BPG * SH_ROW)     // 68 float4 per warp
#define SX_ROW  5                  // float4 stride per x row (4 + 1 pad)
#define SX_PW   (BPG * SX_ROW)     // 20 float4 per warp
#define RED_STRIDE 33

// Bounded spin (converts pathological stall into wrong answer, not a hang)
#define SPIN_LIMIT (1u << 22)

// Per-group cumulative step flags, 128B apart; reset via cudaMemsetAsync each launch.
__device__ unsigned g_flags[NGRP * 32];

// Packed dual-FMA: acc.{lo,hi} += a.{lo,hi} * b.{lo,hi}
#define FMA2(acc, a, b) \
    asm("fma.rn.f32x2 %0, %1, %2, %0;" : "+l"(acc) : "l"(a), "l"(b))

__global__ __launch_bounds__(THREADS, 1)
void rnn_2chain_kernel(const float* __restrict__ x,
                       const float* __restrict__ Wi,
                       const float* __restrict__ bi,
                       const float* __restrict__ Wh,
                       const float* __restrict__ bh,
                       float* __restrict__ out)
{
    __shared__ float4 sh[NWARP * SH_PW];     // per-warp h stage (both chains reuse)
    __shared__ float4 sx[NWARP * SX_PW];     // per-warp x stage
    __shared__ float  sred[32 * RED_STRIDE]; // cross-warp partial reduction

    const int tid  = threadIdx.x;
    const int bx   = blockIdx.x;
    const int q    = bx >> 4;
    const int jt   = bx & 15;
    const int lane = tid & 31;
    const int w    = tid >> 5;               // warp = K-slice owner
    const int jg   = jt * 32 + lane;         // this lane's output column

    unsigned* flg[2] = { &g_flags[(2 * q) * 32], &g_flags[(2 * q + 1) * 32] };
    const int bb[2]  = { q * 8, q * 8 + 4 }; // batch bases of chains A,B

    // ---- Weights into registers (one-time). Warp w owns K floats [w*64,w*64+64) of Wh
    // and [w*16,w*16+16) of Wi, for this lane's row jg.
    ulonglong2 wq[WHC], wiv[WIC];
    {
        const ulonglong2* p = (const ulonglong2*)(Wh + (size_t)jg * HDIM);
        #pragma unroll
        for (int c = 0; c < WHC; c++) wq[c] = __ldg(&p[w * WHC + c]);
        const ulonglong2* pi = (const ulonglong2*)(Wi + (size_t)jg * INDIM);
        #pragma unroll
        for (int c = 0; c < WIC; c++) wiv[c] = __ldg(&pi[w * WIC + c]);
    }
    const float cb = bi[jg] + bh[jg];

    float4* shw = sh + w * SH_PW;
    float4* sxw = sx + w * SX_PW;
    const ulonglong2* shw2 = (const ulonglong2*)shw;  // 16B view (== float4)
    const ulonglong2* sxw2 = (const ulonglong2*)sxw;

    // Prefetch lane roles
    const int hr = lane >> 3, hc = lane & 7;   // h: 4 rows x 16 f4; 2 f4/lane
    const int xr = lane >> 2, xc = lane & 3;   // x: 4 rows x 4 f4; lanes<16, 1 f4

    float4 hp0[2], hp1[2], xp[2];
    // Pre-loop: x for chain A step 0
    if (lane < 16)
        xp[0] = ((const float4*)x)[((size_t)0 * BATCH + bb[0] + xr) * (INDIM / 4)
                                   + w * WIC + xc];
    __syncthreads();

    for (int t = 0; t < SEQ; t++) {
        #pragma unroll
        for (int c = 0; c < 2; c++) {
            const int nc = c ^ 1;
            const int tn = (c == 0) ? t : t + 1;   // step of the NEXT phase (chain nc)

            // -- 1. Stage prefetched h / x into this warp's smem region
            if (t > 0) {
                shw[hr * SH_ROW + hc]     = hp0[c];
                shw[hr * SH_ROW + hc + 8] = hp1[c];
            }
            if (lane < 16) sxw[xr * SX_ROW + xc] = xp[c];
            __syncwarp();

            // -- 2. Partial dot products (weights in regs, operands via smem broadcast)
            unsigned long long acc[BPG];
            #pragma unroll
            for (int b = 0; b < BPG; b++) acc[b] = 0ull;

            #pragma unroll
            for (int ic = 0; ic < WIC; ic++) {
                #pragma unroll
                for (int b = 0; b < BPG; b++) {
                    ulonglong2 hv = sxw2[b * SX_ROW + ic];
                    FMA2(acc[b], wiv[ic].x, hv.x);
                    FMA2(acc[b], wiv[ic].y, hv.y);
                }
            }
            if (t > 0) {
                #pragma unroll
                for (int k = 0; k < WHC; k++) {
                    #pragma unroll
                    for (int b = 0; b < BPG; b++) {
                        ulonglong2 hv = shw2[b * SH_ROW + k];
                        FMA2(acc[b], wq[k].x, hv.x);
                        FMA2(acc[b], wq[k].y, hv.y);
                    }
                }
            }

            // -- 3. Spill partials: sred[j=lane][b*8+w] (stride 33 -> conflict-free)
            #pragma unroll
            for (int b = 0; b < BPG; b++) {
                union { unsigned long long u; float2 f; } cv; cv.u = acc[b];
                sred[lane * RED_STRIDE + b * NWARP + w] = cv.f.x + cv.f.y;
            }
            __syncthreads();                       // bar1: spill -> read

            // -- 4. Warps 0-3: reduce + tanh + store. Warp 7 lane 0: poll next chain.
            if (w < 4) {
                const float* r = &sred[lane * RED_STRIDE + w * NWARP];
                float s = ((r[0] + r[1]) + (r[2] + r[3]))
                        + ((r[4] + r[5]) + (r[6] + r[7]));
                const float val = tanhf(cb + s);
                out[((size_t)t * BATCH + bb[c] + w) * HDIM + jg] = val;
                if (t == SEQ - 1)   // h_last row appended after h_seq
                    out[((size_t)SEQ * BATCH + bb[c] + w) * HDIM + jg] = val;
            } else if (w == 7 && lane == 0 && tn >= 1 && tn < SEQ) {
                // next phase (chain nc, step tn) needs h_nc(tn-1): flag >= 16*tn
                const unsigned target = (unsigned)(NJ * tn);
                unsigned v, it = 0;
                do {
                    asm volatile("ld.acquire.gpu.global.u32 %0, [%1];"
                                 : "=r"(v) : "l"(flg[nc]) : "memory");
                } while (v < target && ++it < SPIN_LIMIT);
            }
            __syncthreads();                       // bar2: stores+poll done CTA-wide

            // -- 5. Publish this chain's step t (single release; bar2 gave CTA HB)
            if (tid == 0)
                asm volatile("red.release.gpu.global.add.u32 [%0], %1;"
                             :: "l"(flg[c]), "r"(1u) : "memory");

            // -- 6. Prefetch next phase's operands (poll already confirmed readiness)
            if (tn < SEQ) {
                if (tn >= 1) {
                    const float4* hs =
                        (const float4*)(out + (size_t)(tn - 1) * BATCH * HDIM);
                    hp0[nc] = hs[(bb[nc] + hr) * (HDIM / 4) + w * WHC + hc];
                    hp1[nc] = hs[(bb[nc] + hr) * (HDIM / 4) + w * WHC + hc + 8];
                }
                if (lane < 16)
                    xp[nc] = ((const float4*)x)[((size_t)tn * BATCH + bb[nc] + xr)
                                                * (INDIM / 4) + w * WIC + xc];
            }
        }
    }
}

extern "C" void kernel_launch(void* const* d_in, const int* in_sizes, int n_in,
                              void* d_out, int out_size)
{
    const float* x  = (const float*)d_in[0];
    const float* Wi = (const float*)d_in[1];
    const float* bi = (const float*)d_in[2];
    const float* Wh = (const float*)d_in[3];
    const float* bh = (const float*)d_in[4];
    float* out = (float*)d_out;

    (void)in_sizes; (void)n_in; (void)out_size;

    void* flagsPtr = nullptr;
    cudaGetSymbolAddress(&flagsPtr, g_flags);
    cudaMemsetAsync(flagsPtr, 0, sizeof(g_flags), 0);

    rnn_2chain_kernel<<<NCTA, THREADS>>>(x, Wi, bi, Wh, bh, out);
}